// round 7
// baseline (speedup 1.0000x reference)
#include <cuda_runtime.h>
#include <cuda_fp16.h>

// kendallloss: 1 - 2 * [sum_{i>j} clip(p_i-p_j)*clip(t_i-t_j)] / (N*(N-1))
//
// f16x2 sat-trick, exact-per-pair q (R4 scheme, restored):
//   pd = sat(0.5*p_i + (0.5 - 0.5*p_j)) == (clip(p_i-p_j)+1)/2   (HADD2.SAT)
//   td = likewise                                                 (HADD2.SAT)
//   q  = 4*pd*td - 2*(pd+td) + 1  (orientation-symmetric -> weight-2 triangle OK)
// Inner: 5 half2 ops per 2 pairs: 2x HADD2.SAT, HFMA2 (P), 2x HADD2 (S).
//
// This round: occupancy/balance fix. accS reduced 8->4 regs (q&3) and
// __launch_bounds__(256,7) => <=36 regs => 7 blocks/SM => n_conc=1036 =>
// grid 2080 = 2.008 waves (near-zero wave-quantization tail, was 2.34->3).

#define MAXN 32768
#define TILE 256
#define RI   8

__device__ double       g_part[(MAXN / TILE) * (MAXN / TILE + 1) / 2];
__device__ unsigned int g_done = 0;

__global__ __launch_bounds__(256, 7) void pair_kernel(const float* __restrict__ p,
                                                      const float* __restrict__ tg,
                                                      float* __restrict__ out,
                                                      int n, int nblocks) {
    const int b = blockIdx.x;
    // Decode lower-triangle tile index: b -> (bi, bj), bj <= bi.
    int r = (int)((sqrtf(8.0f * (float)b + 1.0f) - 1.0f) * 0.5f);
    while ((r + 1) * (r + 2) / 2 <= b) r++;
    while (r * (r + 1) / 2 > b) r--;
    const int bi = r;
    const int bj = b - r * (r + 1) / 2;

    const int t = threadIdx.x;
    const int ibase = bi * TILE;
    const int jbase = bj * TILE;

    // Stage j-side tile: 128 half2 pairs of {b_p, b_t}, b = 0.5 - 0.5*x[j].
    __shared__ uint2 sj[TILE / 2];
    if (t < TILE / 2) {
        float2 pv = *(const float2*)(p  + jbase + 2 * t);
        float2 tv = *(const float2*)(tg + jbase + 2 * t);
        __half2 bp = __floats2half2_rn(0.5f - 0.5f * pv.x, 0.5f - 0.5f * pv.y);
        __half2 bt = __floats2half2_rn(0.5f - 0.5f * tv.x, 0.5f - 0.5f * tv.y);
        uint2 u;
        u.x = *(unsigned int*)&bp;
        u.y = *(unsigned int*)&bt;
        sj[t] = u;
    }

    // i-side registers: a = 0.5*x[i], broadcast into both half2 lanes.
    const int ig = t & 31;
    const int jg = t >> 5;
    const int i0 = ibase + ig * RI;
    const int s0 = jg * 16;

    float4 pf0 = *(const float4*)(p  + i0);
    float4 pf1 = *(const float4*)(p  + i0 + 4);
    float4 tf0 = *(const float4*)(tg + i0);
    float4 tf1 = *(const float4*)(tg + i0 + 4);

    __half2 ap[RI], at[RI], accP[RI], accS[4];
    {
        float pv[RI] = {pf0.x, pf0.y, pf0.z, pf0.w, pf1.x, pf1.y, pf1.z, pf1.w};
        float tv[RI] = {tf0.x, tf0.y, tf0.z, tf0.w, tf1.x, tf1.y, tf1.z, tf1.w};
#pragma unroll
        for (int q = 0; q < RI; q++) {
            ap[q]   = __half2half2(__float2half_rn(0.5f * pv[q]));
            at[q]   = __half2half2(__float2half_rn(0.5f * tv[q]));
            accP[q] = __float2half2_rn(0.0f);
        }
#pragma unroll
        for (int q = 0; q < 4; q++) accS[q] = __float2half2_rn(0.0f);
    }
    __syncthreads();

#pragma unroll
    for (int s = 0; s < 16; s++) {
        uint2 v = sj[s0 + s];            // warp-uniform broadcast (no conflicts)
        __half2 bp2 = *(__half2*)&v.x;
        __half2 bt2 = *(__half2*)&v.y;
#pragma unroll
        for (int q = 0; q < RI; q++) {
            __half2 pd = __hadd2_sat(ap[q], bp2);   // (clip(p_i-p_j)+1)/2
            __half2 td = __hadd2_sat(at[q], bt2);   // (clip(t_i-t_j)+1)/2
            accP[q] = __hfma2(pd, td, accP[q]);     // P partial
            __half2 sm = __hadd2(pd, td);
            accS[q & 3] = __hadd2(accS[q & 3], sm); // S partial (<=64 per reg)
        }
    }

    // Per-thread combine in fp32: q_sum = 4P - 2S + count (256 pairs/thread)
    float faP = 0.0f, faS = 0.0f;
#pragma unroll
    for (int q = 0; q < RI; q++) {
        float2 f = __half22float2(accP[q]);
        faP += f.x + f.y;
    }
#pragma unroll
    for (int q = 0; q < 4; q++) {
        float2 f = __half22float2(accS[q]);
        faS += f.x + f.y;
    }
    float qth = 4.0f * faP - 2.0f * faS + 256.0f;

    // Deterministic block reduction
#pragma unroll
    for (int off = 16; off; off >>= 1)
        qth += __shfl_down_sync(0xffffffffu, qth, off);
    __shared__ float wsum[8];
    if ((t & 31) == 0) wsum[t >> 5] = qth;
    __syncthreads();

    __shared__ int s_last;
    if (t == 0) {
        float bs = 0.0f;
#pragma unroll
        for (int w = 0; w < 8; w++) bs += wsum[w];
        double wgt = (bi == bj) ? 1.0 : 2.0;   // off-diag tile covers both orientations
        g_part[b] = wgt * (double)bs;
        __threadfence();
        unsigned int done = atomicAdd(&g_done, 1u);
        s_last = (done == (unsigned int)(nblocks - 1));
    }
    __syncthreads();

    if (s_last) {
        // Last block: fixed-order double reduction over all tile partials.
        __shared__ double sd[256];
        double s = 0.0;
        for (int k = t; k < nblocks; k += 256) s += g_part[k];
        sd[t] = s;
        __syncthreads();
        for (int off = 128; off; off >>= 1) {
            if (t < off) sd[t] += sd[t + off];
            __syncthreads();
        }
        if (t == 0) {
            double denom = (double)n * (double)(n - 1);
            out[0] = (float)(1.0 - sd[0] / denom);   // 1 - full_sum/denom
            g_done = 0;                               // reset for next graph replay
        }
    }
}

extern "C" void kernel_launch(void* const* d_in, const int* in_sizes, int n_in,
                              void* d_out, int out_size) {
    const float* p = (const float*)d_in[0];
    const float* t = (const float*)d_in[1];
    int n = in_sizes[0];              // 16384, divisible by TILE

    int T  = n / TILE;
    int nb = T * (T + 1) / 2;         // 2080 lower-triangle tiles
    pair_kernel<<<nb, 256>>>(p, t, (float*)d_out, n, nb);
}

// round 10
// speedup vs baseline: 1.1604x; 1.1604x over previous
#include <cuda_runtime.h>
#include <cuda_fp16.h>

// kendallloss: 1 - 2 * [sum_{i>j} clip(p_i-p_j)*clip(t_i-t_j)] / (N*(N-1))
//
// Pipe-split formulation: exact per-pair clamp product.
//   pd = max(min(p_i + (-p_j), 1), -1)   HADD2 (fma) + 2x HMNMX2 (alu)
//   td = likewise                         HADD2 (fma) + 2x HMNMX2 (alu)
//   acc += pd*td                          HFMA2 (fma)
// Per half2 slot: 3 fma-pipe ops + 4 alu-pipe ops running CONCURRENTLY
// (alu pipe was 95% idle in the 5-op all-fma sat-trick version).
// fp16 accumulator over 16 steps (|acc|<=16), flushed to fp32 per tile.
//
// Triangle tiling 256x256: off-diag tiles weight 2, diag tiles weight 1.
// Single kernel; last block (atomic ticket) does the double reduction.
//
// (R8 resubmission: R7 run died with a device-busy infra error before launch.)

#define MAXN 32768
#define TILE 256
#define RI   8

__device__ double       g_part[(MAXN / TILE) * (MAXN / TILE + 1) / 2];
__device__ unsigned int g_done = 0;

__global__ __launch_bounds__(256, 7) void pair_kernel(const float* __restrict__ p,
                                                      const float* __restrict__ tg,
                                                      float* __restrict__ out,
                                                      int n, int nblocks) {
    const int b = blockIdx.x;
    // Decode lower-triangle tile index: b -> (bi, bj), bj <= bi.
    int r = (int)((sqrtf(8.0f * (float)b + 1.0f) - 1.0f) * 0.5f);
    while ((r + 1) * (r + 2) / 2 <= b) r++;
    while (r * (r + 1) / 2 > b) r--;
    const int bi = r;
    const int bj = b - r * (r + 1) / 2;

    const int t = threadIdx.x;
    const int ibase = bi * TILE;
    const int jbase = bj * TILE;

    // Stage j-side tile: 128 half2 pairs of {-p[j], -t[j]}.
    __shared__ uint2 sj[TILE / 2];
    if (t < TILE / 2) {
        float2 pv = *(const float2*)(p  + jbase + 2 * t);
        float2 tv = *(const float2*)(tg + jbase + 2 * t);
        __half2 np = __floats2half2_rn(-pv.x, -pv.y);
        __half2 nt = __floats2half2_rn(-tv.x, -tv.y);
        uint2 u;
        u.x = *(unsigned int*)&np;
        u.y = *(unsigned int*)&nt;
        sj[t] = u;
    }

    // i-side registers: raw values broadcast into both half2 lanes.
    const int ig = t & 31;
    const int jg = t >> 5;
    const int i0 = ibase + ig * RI;
    const int s0 = jg * 16;

    float4 pf0 = *(const float4*)(p  + i0);
    float4 pf1 = *(const float4*)(p  + i0 + 4);
    float4 tf0 = *(const float4*)(tg + i0);
    float4 tf1 = *(const float4*)(tg + i0 + 4);

    __half2 ap[RI], at[RI], accP[RI];
    {
        float pv[RI] = {pf0.x, pf0.y, pf0.z, pf0.w, pf1.x, pf1.y, pf1.z, pf1.w};
        float tv[RI] = {tf0.x, tf0.y, tf0.z, tf0.w, tf1.x, tf1.y, tf1.z, tf1.w};
#pragma unroll
        for (int q = 0; q < RI; q++) {
            ap[q]   = __half2half2(__float2half_rn(pv[q]));
            at[q]   = __half2half2(__float2half_rn(tv[q]));
            accP[q] = __float2half2_rn(0.0f);
        }
    }
    const __half2 one2  = __float2half2_rn(1.0f);
    const __half2 mone2 = __float2half2_rn(-1.0f);
    __syncthreads();

#pragma unroll
    for (int s = 0; s < 16; s++) {
        uint2 v = sj[s0 + s];            // warp-uniform broadcast (no conflicts)
        __half2 np2 = *(__half2*)&v.x;
        __half2 nt2 = *(__half2*)&v.y;
#pragma unroll
        for (int q = 0; q < RI; q++) {
            __half2 pd = __hadd2(ap[q], np2);       // fma pipe
            pd = __hmin2(pd, one2);                 // alu pipe (hypothesis)
            pd = __hmax2(pd, mone2);                // alu pipe (hypothesis)
            __half2 td = __hadd2(at[q], nt2);       // fma pipe
            td = __hmin2(td, one2);                 // alu pipe (hypothesis)
            td = __hmax2(td, mone2);                // alu pipe (hypothesis)
            accP[q] = __hfma2(pd, td, accP[q]);     // fma pipe
        }
    }

    // Flush to fp32
    float faP = 0.0f;
#pragma unroll
    for (int q = 0; q < RI; q++) {
        float2 f = __half22float2(accP[q]);
        faP += f.x + f.y;
    }

    // Deterministic block reduction
#pragma unroll
    for (int off = 16; off; off >>= 1)
        faP += __shfl_down_sync(0xffffffffu, faP, off);
    __shared__ float wsum[8];
    if ((t & 31) == 0) wsum[t >> 5] = faP;
    __syncthreads();

    __shared__ int s_last;
    if (t == 0) {
        float bs = 0.0f;
#pragma unroll
        for (int w = 0; w < 8; w++) bs += wsum[w];
        double wgt = (bi == bj) ? 1.0 : 2.0;   // off-diag tile covers both orientations
        g_part[b] = wgt * (double)bs;
        __threadfence();
        unsigned int done = atomicAdd(&g_done, 1u);
        s_last = (done == (unsigned int)(nblocks - 1));
    }
    __syncthreads();

    if (s_last) {
        // Last block: fixed-order double reduction over all tile partials.
        __shared__ double sd[256];
        double s = 0.0;
        for (int k = t; k < nblocks; k += 256) s += g_part[k];
        sd[t] = s;
        __syncthreads();
        for (int off = 128; off; off >>= 1) {
            if (t < off) sd[t] += sd[t + off];
            __syncthreads();
        }
        if (t == 0) {
            double denom = (double)n * (double)(n - 1);
            out[0] = (float)(1.0 - sd[0] / denom);   // 1 - full_sum/denom
            g_done = 0;                               // reset for next graph replay
        }
    }
}

extern "C" void kernel_launch(void* const* d_in, const int* in_sizes, int n_in,
                              void* d_out, int out_size) {
    const float* p = (const float*)d_in[0];
    const float* t = (const float*)d_in[1];
    int n = in_sizes[0];              // 16384, divisible by TILE

    int T  = n / TILE;
    int nb = T * (T + 1) / 2;         // 2080 lower-triangle tiles
    pair_kernel<<<nb, 256>>>(p, t, (float*)d_out, n, nb);
}